// round 1
// baseline (speedup 1.0000x reference)
#include <cuda_runtime.h>
#include <cstdint>

// Problem constants
#define VOCAB 50000
#define BT    16384         // B*T = 32*512
#define DOUT  256
#define K0    300
#define K1    300
#define K2    200
#define KTOT  800
#define KC    20            // K-chunk; 300%20==0 and 600%20==0 -> chunks never straddle segments
#define TM    128
#define TN    128

// Scratch (device globals: no allocation allowed)
__device__ float g_u[KTOT];      // [W0;W1;W2] @ Wa
__device__ float g_c[3];         // b_n . Wa + ba
__device__ float g_alpha[BT*3];  // softmax weights per token

// ---------------------------------------------------------------------------
// Kernel A: u = concat(W0,W1,W2) @ Wa ; c[n] = b_n . Wa + ba
// ---------------------------------------------------------------------------
__global__ void prep_kernel(const float* __restrict__ W0, const float* __restrict__ b0,
                            const float* __restrict__ W1, const float* __restrict__ b1,
                            const float* __restrict__ W2, const float* __restrict__ b2,
                            const float* __restrict__ Wa, const float* __restrict__ ba)
{
    int warp = (blockIdx.x * blockDim.x + threadIdx.x) >> 5;
    int lane = threadIdx.x & 31;
    if (warp < KTOT) {
        const float* row;
        if (warp < K0)          row = W0 + (long)warp * DOUT;
        else if (warp < K0+K1)  row = W1 + (long)(warp - K0) * DOUT;
        else                    row = W2 + (long)(warp - K0 - K1) * DOUT;
        float s = 0.f;
        for (int d = lane; d < DOUT; d += 32) s += row[d] * Wa[d];
        #pragma unroll
        for (int o = 16; o; o >>= 1) s += __shfl_xor_sync(0xffffffffu, s, o);
        if (lane == 0) g_u[warp] = s;
    } else if (warp < KTOT + 3) {
        int n = warp - KTOT;
        const float* b = (n == 0) ? b0 : ((n == 1) ? b1 : b2);
        float s = 0.f;
        for (int d = lane; d < DOUT; d += 32) s += b[d] * Wa[d];
        #pragma unroll
        for (int o = 16; o; o >>= 1) s += __shfl_xor_sync(0xffffffffu, s, o);
        if (lane == 0) g_c[n] = s + ba[0];
    }
}

// ---------------------------------------------------------------------------
// Kernel B: per-token logits via e_n . u_n, then 3-way softmax -> g_alpha
// One warp per token.
// ---------------------------------------------------------------------------
__global__ void alpha_kernel(const int* __restrict__ ids,
                             const float* __restrict__ E0,
                             const float* __restrict__ E1,
                             const float* __restrict__ E2)
{
    __shared__ float su[KTOT];
    __shared__ float sc[3];
    for (int i = threadIdx.x; i < KTOT; i += blockDim.x) su[i] = g_u[i];
    if (threadIdx.x < 3) sc[threadIdx.x] = g_c[threadIdx.x];
    __syncthreads();

    int warp = (blockIdx.x * blockDim.x + threadIdx.x) >> 5;
    int lane = threadIdx.x & 31;
    if (warp >= BT) return;

    long id = (long)ids[warp];
    float l0 = 0.f, l1 = 0.f, l2 = 0.f;
    const float* r0 = E0 + id * K0;
    for (int k = lane; k < K0; k += 32) l0 += r0[k] * su[k];
    const float* r1 = E1 + id * K1;
    for (int k = lane; k < K1; k += 32) l1 += r1[k] * su[K0 + k];
    const float* r2 = E2 + id * K2;
    for (int k = lane; k < K2; k += 32) l2 += r2[k] * su[K0 + K1 + k];

    #pragma unroll
    for (int o = 16; o; o >>= 1) {
        l0 += __shfl_xor_sync(0xffffffffu, l0, o);
        l1 += __shfl_xor_sync(0xffffffffu, l1, o);
        l2 += __shfl_xor_sync(0xffffffffu, l2, o);
    }
    if (lane == 0) {
        l0 += sc[0]; l1 += sc[1]; l2 += sc[2];
        float m  = fmaxf(l0, fmaxf(l1, l2));
        float e0 = expf(l0 - m), e1 = expf(l1 - m), e2 = expf(l2 - m);
        float inv = 1.f / (e0 + e1 + e2);
        g_alpha[warp*3 + 0] = e0 * inv;
        g_alpha[warp*3 + 1] = e1 * inv;
        g_alpha[warp*3 + 2] = e2 * inv;
    }
}

// ---------------------------------------------------------------------------
// Kernel C: out[16384,256] = (alpha-scaled gathered A)[16384,800] @ W[800,256]
//           + sum_n alpha_n * b_n
// Tile: TM=128 tokens x TN=128 dims, 256 threads, 8x8 micro-tiles.
// ---------------------------------------------------------------------------
__global__ void __launch_bounds__(256, 2)
gemm_kernel(const int*   __restrict__ ids,
            const float* __restrict__ E0, const float* __restrict__ E1, const float* __restrict__ E2,
            const float* __restrict__ W0, const float* __restrict__ b0,
            const float* __restrict__ W1, const float* __restrict__ b1,
            const float* __restrict__ W2, const float* __restrict__ b2,
            float* __restrict__ out)
{
    __shared__ float As[KC][TM];
    __shared__ float Bs[KC][TN + 4];
    __shared__ float sAlpha[3][TM];
    __shared__ int   sId[TM];
    __shared__ float sBias[3][TN];

    const int tid = threadIdx.x;
    const int m0 = blockIdx.x * TM;
    const int n0 = blockIdx.y * TN;

    for (int i = tid; i < TM; i += 256) {
        int t = m0 + i;
        sId[i]       = ids[t];
        sAlpha[0][i] = g_alpha[t*3 + 0];
        sAlpha[1][i] = g_alpha[t*3 + 1];
        sAlpha[2][i] = g_alpha[t*3 + 2];
    }
    for (int i = tid; i < TN; i += 256) {
        sBias[0][i] = b0[n0 + i];
        sBias[1][i] = b1[n0 + i];
        sBias[2][i] = b2[n0 + i];
    }
    __syncthreads();

    float acc[8][8];
    #pragma unroll
    for (int i = 0; i < 8; i++)
        #pragma unroll
        for (int j = 0; j < 8; j++) acc[i][j] = 0.f;

    const int tx = tid & 15;   // 16 cols of threads
    const int ty = tid >> 4;   // 16 rows of threads

    #pragma unroll 1
    for (int kc = 0; kc < KTOT / KC; kc++) {
        const int k0 = kc * KC;
        int seg, kl, Klen;
        const float* E; const float* W;
        if (k0 < K0)            { seg = 0; kl = k0;            E = E0; W = W0; Klen = K0; }
        else if (k0 < K0 + K1)  { seg = 1; kl = k0 - K0;       E = E1; W = W1; Klen = K1; }
        else                    { seg = 2; kl = k0 - K0 - K1;  E = E2; W = W2; Klen = K2; }

        // --- load A tile: TM tokens x KC k  (alpha-scaled, transposed into As[k][t]) ---
        // 640 float4 loads; 5 consecutive float4 per token row -> good request coalescing
        #pragma unroll
        for (int it = 0; it < 3; it++) {
            int idx = tid + it * 256;
            if (idx < TM * (KC/4)) {
                int t  = idx / (KC/4);
                int kq = idx % (KC/4);
                const float4 v = *(const float4*)(E + (long)sId[t] * Klen + kl + kq*4);
                float a = sAlpha[seg][t];
                int kk = kq * 4;
                As[kk+0][t] = v.x * a;
                As[kk+1][t] = v.y * a;
                As[kk+2][t] = v.z * a;
                As[kk+3][t] = v.w * a;
            }
        }
        // --- load B tile: KC x TN from W (row stride DOUT) ---
        #pragma unroll
        for (int it = 0; it < 3; it++) {
            int idx = tid + it * 256;
            if (idx < KC * (TN/4)) {
                int r  = idx / (TN/4);
                int c4 = idx % (TN/4);
                float4 v = *(const float4*)(W + (long)(kl + r) * DOUT + n0 + c4*4);
                *(float4*)&Bs[r][c4*4] = v;
            }
        }
        __syncthreads();

        #pragma unroll
        for (int kk = 0; kk < KC; kk++) {
            float ra[8], rb[8];
            *(float4*)&ra[0] = *(const float4*)&As[kk][ty*4];
            *(float4*)&ra[4] = *(const float4*)&As[kk][64 + ty*4];
            *(float4*)&rb[0] = *(const float4*)&Bs[kk][tx*4];
            *(float4*)&rb[4] = *(const float4*)&Bs[kk][64 + tx*4];
            #pragma unroll
            for (int i = 0; i < 8; i++)
                #pragma unroll
                for (int j = 0; j < 8; j++)
                    acc[i][j] += ra[i] * rb[j];
        }
        __syncthreads();
    }

    // --- epilogue: add alpha-weighted biases, store float4 ---
    #pragma unroll
    for (int i = 0; i < 8; i++) {
        int t = (i < 4) ? (ty*4 + i) : (64 + ty*4 + (i - 4));
        float a0 = sAlpha[0][t], a1 = sAlpha[1][t], a2 = sAlpha[2][t];
        long tglob = m0 + t;
        #pragma unroll
        for (int jg = 0; jg < 2; jg++) {
            int c = (jg == 0) ? (tx*4) : (64 + tx*4);
            float4 v;
            v.x = acc[i][jg*4+0] + a0*sBias[0][c+0] + a1*sBias[1][c+0] + a2*sBias[2][c+0];
            v.y = acc[i][jg*4+1] + a0*sBias[0][c+1] + a1*sBias[1][c+1] + a2*sBias[2][c+1];
            v.z = acc[i][jg*4+2] + a0*sBias[0][c+2] + a1*sBias[1][c+2] + a2*sBias[2][c+2];
            v.w = acc[i][jg*4+3] + a0*sBias[0][c+3] + a1*sBias[1][c+3] + a2*sBias[2][c+3];
            *(float4*)(out + tglob * DOUT + n0 + c) = v;
        }
    }
}

// ---------------------------------------------------------------------------
extern "C" void kernel_launch(void* const* d_in, const int* in_sizes, int n_in,
                              void* d_out, int out_size)
{
    const int*   ids = (const int*)  d_in[0];
    const float* E0  = (const float*)d_in[1];
    const float* E1  = (const float*)d_in[2];
    const float* E2  = (const float*)d_in[3];
    const float* W0  = (const float*)d_in[4];
    const float* b0  = (const float*)d_in[5];
    const float* W1  = (const float*)d_in[6];
    const float* b1  = (const float*)d_in[7];
    const float* W2  = (const float*)d_in[8];
    const float* b2  = (const float*)d_in[9];
    const float* Wa  = (const float*)d_in[10];
    const float* ba  = (const float*)d_in[11];
    float* out = (float*)d_out;

    // A: u = W@Wa (803 warps of work)
    prep_kernel<<<101, 256>>>(W0, b0, W1, b1, W2, b2, Wa, ba);
    // B: softmax weights, one warp per token
    alpha_kernel<<<BT/8, 256>>>(ids, E0, E1, E2);
    // C: fused scaled-gather GEMM + bias
    dim3 grid(BT / TM, DOUT / TN);
    gemm_kernel<<<grid, 256>>>(ids, E0, E1, E2, W0, b0, W1, b1, W2, b2, out);
}

// round 5
// speedup vs baseline: 1.6139x; 1.6139x over previous
#include <cuda_runtime.h>
#include <cuda_bf16.h>
#include <cstdint>

// ---------------------------------------------------------------------------
// Problem constants
// ---------------------------------------------------------------------------
#define BT     16384          // B*T tokens
#define DOUT   256
#define K0     300
#define K1     300
#define K2     200
#define KTOT   800
#define KPAD   832            // 13 * 64, zero padded
#define NCHUNK 13

// GEMM tiling
#define BM 128
#define BN 128
#define BK 64
#define STAGES 3
#define SPITCH 72                             // bf16 elems per smem row (64 + 8 pad)
#define STAGE_BYTES ((BM + BN) * SPITCH * 2)  // 36864
#define DYN_SMEM (STAGES * STAGE_BYTES)       // 110592

// ---------------------------------------------------------------------------
// Device-global scratch (no allocations allowed)
// ---------------------------------------------------------------------------
__device__ float g_u[KTOT];
__device__ float g_c[3];
__device__ float g_alpha[BT * 3];
__device__ __align__(16) __nv_bfloat16 g_Ahi[(size_t)BT * KPAD];
__device__ __align__(16) __nv_bfloat16 g_Alo[(size_t)BT * KPAD];
__device__ __align__(16) __nv_bfloat16 g_Whi[(size_t)DOUT * KPAD];   // [n][k] (W transposed)
__device__ __align__(16) __nv_bfloat16 g_Wlo[(size_t)DOUT * KPAD];

// ---------------------------------------------------------------------------
// Helpers
// ---------------------------------------------------------------------------
__device__ __forceinline__ uint32_t su32(const void* p) {
    uint32_t a;
    asm("{ .reg .u64 t; cvta.to.shared.u64 t, %1; cvt.u32.u64 %0, t; }" : "=r"(a) : "l"(p));
    return a;
}
__device__ __forceinline__ void cpa16(uint32_t dst, const void* src) {
    asm volatile("cp.async.cg.shared.global [%0], [%1], 16;" :: "r"(dst), "l"(src) : "memory");
}
#define LDSM4(r, addr) \
    asm volatile("ldmatrix.sync.aligned.m8n8.x4.shared.b16 {%0,%1,%2,%3}, [%4];" \
                 : "=r"((r)[0]), "=r"((r)[1]), "=r"((r)[2]), "=r"((r)[3]) : "r"(addr))
#define MMA16816(d, a, bb0, bb1) \
    asm volatile("mma.sync.aligned.m16n8k16.row.col.f32.bf16.bf16.f32 " \
                 "{%0,%1,%2,%3}, {%4,%5,%6,%7}, {%8,%9}, {%0,%1,%2,%3};" \
                 : "+f"((d)[0]), "+f"((d)[1]), "+f"((d)[2]), "+f"((d)[3]) \
                 : "r"((a)[0]), "r"((a)[1]), "r"((a)[2]), "r"((a)[3]), "r"(bb0), "r"(bb1))

// Split fp32 pair -> packed bf16 hi / lo words
__device__ __forceinline__ void split2(float v0, float v1, uint32_t& hi, uint32_t& lo) {
    __nv_bfloat16 h0 = __float2bfloat16_rn(v0);
    __nv_bfloat16 h1 = __float2bfloat16_rn(v1);
    float r0 = v0 - __bfloat162float(h0);
    float r1 = v1 - __bfloat162float(h1);
    __nv_bfloat16 l0 = __float2bfloat16_rn(r0);
    __nv_bfloat16 l1 = __float2bfloat16_rn(r1);
    hi = (uint32_t)__bfloat16_as_ushort(h0) | ((uint32_t)__bfloat16_as_ushort(h1) << 16);
    lo = (uint32_t)__bfloat16_as_ushort(l0) | ((uint32_t)__bfloat16_as_ushort(l1) << 16);
}

// ---------------------------------------------------------------------------
// Kernel 1: u = concat(W)@Wa, c = b.Wa + ba  AND  W -> (Whi^T, Wlo^T) bf16
// blocks [0,104): prep.  blocks [104,520): W split.
// ---------------------------------------------------------------------------
__global__ void prepw_kernel(const float* __restrict__ W0, const float* __restrict__ b0,
                             const float* __restrict__ W1, const float* __restrict__ b1,
                             const float* __restrict__ W2, const float* __restrict__ b2,
                             const float* __restrict__ Wa, const float* __restrict__ ba)
{
    const int tid = threadIdx.x;
    if (blockIdx.x < 104) {
        int warp = blockIdx.x * 8 + (tid >> 5);
        int lane = tid & 31;
        if (warp < KTOT) {
            const float* row;
            if (warp < K0)           row = W0 + (size_t)warp * DOUT;
            else if (warp < K0+K1)   row = W1 + (size_t)(warp - K0) * DOUT;
            else                     row = W2 + (size_t)(warp - K0 - K1) * DOUT;
            float s = 0.f;
            for (int d = lane; d < DOUT; d += 32) s += row[d] * Wa[d];
            #pragma unroll
            for (int o = 16; o; o >>= 1) s += __shfl_xor_sync(0xffffffffu, s, o);
            if (lane == 0) g_u[warp] = s;
        } else if (warp < KTOT + 3) {
            int n = warp - KTOT;
            const float* b = (n == 0) ? b0 : ((n == 1) ? b1 : b2);
            float s = 0.f;
            for (int d = lane; d < DOUT; d += 32) s += b[d] * Wa[d];
            #pragma unroll
            for (int o = 16; o; o >>= 1) s += __shfl_xor_sync(0xffffffffu, s, o);
            if (lane == 0) g_c[n] = s + ba[0];
        }
    } else {
        int idx = (blockIdx.x - 104) * 256 + tid;   // [0, 256*416)
        if (idx < DOUT * (KPAD/2)) {
            int n  = idx / (KPAD/2);
            int k  = (idx % (KPAD/2)) * 2;
            float v0 = 0.f, v1 = 0.f;
            if (k < K0)        { v0 = W0[(size_t)k*DOUT + n];       v1 = W0[(size_t)(k+1)*DOUT + n]; }
            else if (k < 600)  { v0 = W1[(size_t)(k-300)*DOUT + n]; v1 = W1[(size_t)(k-299)*DOUT + n]; }
            else if (k < 800)  { v0 = W2[(size_t)(k-600)*DOUT + n]; v1 = W2[(size_t)(k-599)*DOUT + n]; }
            uint32_t hi, lo;
            split2(v0, v1, hi, lo);
            size_t off = ((size_t)n * KPAD + k) * 2;
            *(uint32_t*)((char*)g_Whi + off) = hi;
            *(uint32_t*)((char*)g_Wlo + off) = lo;
        }
    }
}

// ---------------------------------------------------------------------------
// Kernel 2: logits -> softmax alphas, then alpha-scaled split A (row-major)
// One warp per token.
// ---------------------------------------------------------------------------
__global__ void alpha_split_kernel(const int* __restrict__ ids,
                                   const float* __restrict__ E0,
                                   const float* __restrict__ E1,
                                   const float* __restrict__ E2)
{
    __shared__ float su[KTOT];
    __shared__ float sc[3];
    for (int i = threadIdx.x; i < KTOT; i += blockDim.x) su[i] = g_u[i];
    if (threadIdx.x < 3) sc[threadIdx.x] = g_c[threadIdx.x];
    __syncthreads();

    const int warp = blockIdx.x * 8 + (threadIdx.x >> 5);   // token id
    const int lane = threadIdx.x & 31;
    const size_t id = (size_t)ids[warp];

    const float* r0 = E0 + id * K0;
    const float* r1 = E1 + id * K1;
    const float* r2 = E2 + id * K2;

    float l0 = 0.f, l1 = 0.f, l2 = 0.f;
    for (int k = lane; k < K0; k += 32) l0 += r0[k] * su[k];
    for (int k = lane; k < K1; k += 32) l1 += r1[k] * su[K0 + k];
    for (int k = lane; k < K2; k += 32) l2 += r2[k] * su[K0 + K1 + k];
    #pragma unroll
    for (int o = 16; o; o >>= 1) {
        l0 += __shfl_xor_sync(0xffffffffu, l0, o);
        l1 += __shfl_xor_sync(0xffffffffu, l1, o);
        l2 += __shfl_xor_sync(0xffffffffu, l2, o);
    }
    l0 += sc[0]; l1 += sc[1]; l2 += sc[2];
    float m   = fmaxf(l0, fmaxf(l1, l2));
    float e0  = expf(l0 - m), e1 = expf(l1 - m), e2 = expf(l2 - m);
    float inv = 1.f / (e0 + e1 + e2);
    float a0 = e0 * inv, a1 = e1 * inv, a2 = e2 * inv;
    if (lane == 0) {
        g_alpha[warp*3 + 0] = a0;
        g_alpha[warp*3 + 1] = a1;
        g_alpha[warp*3 + 2] = a2;
    }

    #pragma unroll 1
    for (int c = 0; c < NCHUNK; c++) {
        int k = c * 64 + lane * 2;
        float v0 = 0.f, v1 = 0.f;
        if (k < K0)        { v0 = r0[k] * a0;       v1 = r0[k+1] * a0; }
        else if (k < 600)  { v0 = r1[k-300] * a1;   v1 = r1[k-299] * a1; }
        else if (k < 800)  { v0 = r2[k-600] * a2;   v1 = r2[k-599] * a2; }
        uint32_t hi, lo;
        split2(v0, v1, hi, lo);
        size_t off = ((size_t)warp * KPAD + k) * 2;
        *(uint32_t*)((char*)g_Ahi + off) = hi;
        *(uint32_t*)((char*)g_Alo + off) = lo;
    }
}

// ---------------------------------------------------------------------------
// Kernel 3: HMMA GEMM.  out[16384,256] = A[16384,832] @ W^T  (3 bf16 split
// products accumulated in fp32) + alpha-weighted bias.
// CTA: 128x128, 8 warps (4x2), warp tile 32x64, BK=64, 3-stage cp.async.
// ---------------------------------------------------------------------------
__global__ void __launch_bounds__(256, 1)
gemm_kernel(const float* __restrict__ b0, const float* __restrict__ b1,
            const float* __restrict__ b2, float* __restrict__ out)
{
    extern __shared__ __align__(16) __nv_bfloat16 smem[];
    __shared__ float sBias[3][BN];
    __shared__ float sAl[3][BM];

    const int tid  = threadIdx.x;
    const int wid  = tid >> 5;
    const int lane = tid & 31;
    const int m0   = blockIdx.x * BM;
    const int n0   = blockIdx.y * BN;

    for (int i = tid; i < BN; i += 256) {
        sBias[0][i] = b0[n0 + i];
        sBias[1][i] = b1[n0 + i];
        sBias[2][i] = b2[n0 + i];
    }
    for (int i = tid; i < BM; i += 256) {
        int t = m0 + i;
        sAl[0][i] = g_alpha[t*3 + 0];
        sAl[1][i] = g_alpha[t*3 + 1];
        sAl[2][i] = g_alpha[t*3 + 2];
    }

    const uint32_t sb = su32(smem);

    // ---- pipelined load of one (product, chunk) stage ----
    auto loadStage = [&](int iter, int stage) {
        const int p = iter / NCHUNK;
        const int c = iter % NCHUNK;
        const char* Ag = (const char*)((p == 2) ? g_Alo : g_Ahi) + (size_t)m0 * (KPAD*2) + c * 128;
        const char* Bg = (const char*)((p == 1) ? g_Wlo : g_Whi) + (size_t)n0 * (KPAD*2) + c * 128;
        const uint32_t As = sb + stage * STAGE_BYTES;
        const uint32_t Bs = As + BM * SPITCH * 2;
        #pragma unroll
        for (int i = 0; i < 4; i++) {
            int idx = tid + i * 256;
            int row = idx >> 3, cc = idx & 7;
            cpa16(As + (row * SPITCH + cc * 8) * 2, Ag + (size_t)row * (KPAD*2) + cc * 16);
        }
        #pragma unroll
        for (int i = 0; i < 4; i++) {
            int idx = tid + i * 256;
            int row = idx >> 3, cc = idx & 7;
            cpa16(Bs + (row * SPITCH + cc * 8) * 2, Bg + (size_t)row * (KPAD*2) + cc * 16);
        }
        asm volatile("cp.async.commit_group;" ::: "memory");
    };

    float acc[2][8][4];
    #pragma unroll
    for (int mt = 0; mt < 2; mt++)
        #pragma unroll
        for (int nt = 0; nt < 8; nt++)
            #pragma unroll
            for (int j = 0; j < 4; j++) acc[mt][nt][j] = 0.f;

    const int wm = (wid & 3) * 32;     // warp row base
    const int wn = (wid >> 2) * 64;    // warp col base
    const int lr = lane & 15;          // ldmatrix row
    const int lc = lane >> 4;          // ldmatrix k-half

    const int NITER = 3 * NCHUNK;      // 39
    loadStage(0, 0);
    loadStage(1, 1);

    #pragma unroll 1
    for (int iter = 0; iter < NITER; iter++) {
        asm volatile("cp.async.wait_group %0;" :: "n"(STAGES - 2));
        __syncthreads();
        if (iter + STAGES - 1 < NITER)
            loadStage(iter + STAGES - 1, (iter + STAGES - 1) % STAGES);

        const uint32_t As = sb + (iter % STAGES) * STAGE_BYTES;
        const uint32_t Bs = As + BM * SPITCH * 2;

        #pragma unroll
        for (int ks = 0; ks < 4; ks++) {
            uint32_t a[2][4], b[4][4];
            #pragma unroll
            for (int mt = 0; mt < 2; mt++) {
                uint32_t addr = As + ((wm + mt*16 + lr) * SPITCH + ks*16 + lc*8) * 2;
                LDSM4(a[mt], addr);
            }
            #pragma unroll
            for (int nt2 = 0; nt2 < 4; nt2++) {
                uint32_t addr = Bs + ((wn + nt2*16 + lr) * SPITCH + ks*16 + lc*8) * 2;
                LDSM4(b[nt2], addr);
            }
            #pragma unroll
            for (int mt = 0; mt < 2; mt++)
                #pragma unroll
                for (int nt = 0; nt < 8; nt++) {
                    const int g = nt >> 1, h = nt & 1;
                    MMA16816(acc[mt][nt], a[mt], b[g][h], b[g][2 + h]);
                }
        }
    }

    __syncthreads();

    // ---- epilogue: alpha-weighted bias + store ----
    #pragma unroll
    for (int mt = 0; mt < 2; mt++) {
        #pragma unroll
        for (int half = 0; half < 2; half++) {
            const int r  = wm + mt*16 + (lane >> 2) + half*8;
            const float a0 = sAl[0][r], a1 = sAl[1][r], a2 = sAl[2][r];
            float* orow = out + (size_t)(m0 + r) * DOUT + n0;
            #pragma unroll
            for (int nt = 0; nt < 8; nt++) {
                const int cidx = wn + nt*8 + (lane & 3)*2;
                float2 v;
                v.x = acc[mt][nt][half*2 + 0]
                    + a0*sBias[0][cidx]   + a1*sBias[1][cidx]   + a2*sBias[2][cidx];
                v.y = acc[mt][nt][half*2 + 1]
                    + a0*sBias[0][cidx+1] + a1*sBias[1][cidx+1] + a2*sBias[2][cidx+1];
                *(float2*)(orow + cidx) = v;
            }
        }
    }
}

// ---------------------------------------------------------------------------
extern "C" void kernel_launch(void* const* d_in, const int* in_sizes, int n_in,
                              void* d_out, int out_size)
{
    const int*   ids = (const int*)  d_in[0];
    const float* E0  = (const float*)d_in[1];
    const float* E1  = (const float*)d_in[2];
    const float* E2  = (const float*)d_in[3];
    const float* W0  = (const float*)d_in[4];
    const float* b0  = (const float*)d_in[5];
    const float* W1  = (const float*)d_in[6];
    const float* b1  = (const float*)d_in[7];
    const float* W2  = (const float*)d_in[8];
    const float* b2  = (const float*)d_in[9];
    const float* Wa  = (const float*)d_in[10];
    const float* ba  = (const float*)d_in[11];
    float* out = (float*)d_out;

    // Idempotent, host-side, enqueues nothing (safe under graph capture).
    cudaFuncSetAttribute(gemm_kernel, cudaFuncAttributeMaxDynamicSharedMemorySize, DYN_SMEM);

    prepw_kernel<<<520, 256>>>(W0, b0, W1, b1, W2, b2, Wa, ba);
    alpha_split_kernel<<<BT / 8, 256>>>(ids, E0, E1, E2);
    dim3 grid(BT / BM, DOUT / BN);
    gemm_kernel<<<grid, 256, DYN_SMEM>>>(b0, b1, b2, out);   // <-- the R4 bug: smem size was missing
}

// round 6
// speedup vs baseline: 2.9795x; 1.8461x over previous
#include <cuda_runtime.h>
#include <cuda_fp16.h>
#include <cstdint>

// ---------------------------------------------------------------------------
// Problem constants
// ---------------------------------------------------------------------------
#define BT     16384          // B*T tokens
#define DOUT   256
#define K0     300
#define K1     300
#define K2     200
#define KTOT   800
#define KPAD   832            // 13 * 64, zero padded
#define NCHUNK 13

// GEMM tiling
#define BM 128
#define BN 128
#define BK 64
#define STAGES 3
#define SPITCH 72                             // fp16 elems per smem row (64 + 8 pad)
#define STAGE_BYTES ((BM + BN) * SPITCH * 2)  // 36864
#define DYN_SMEM (STAGES * STAGE_BYTES)       // 110592

// ---------------------------------------------------------------------------
// Device-global scratch (no allocations allowed)
// ---------------------------------------------------------------------------
__device__ float g_u[KTOT];
__device__ float g_c[3];
__device__ float g_alpha[BT * 3];
__device__ __align__(16) __half g_Ah[(size_t)BT * KPAD];     // alpha-scaled gathered A, fp16
__device__ __align__(16) __half g_Wh[(size_t)DOUT * KPAD];   // [n][k] (W transposed), fp16

// ---------------------------------------------------------------------------
// Helpers
// ---------------------------------------------------------------------------
__device__ __forceinline__ uint32_t su32(const void* p) {
    uint32_t a;
    asm("{ .reg .u64 t; cvta.to.shared.u64 t, %1; cvt.u32.u64 %0, t; }" : "=r"(a) : "l"(p));
    return a;
}
__device__ __forceinline__ void cpa16(uint32_t dst, const void* src) {
    asm volatile("cp.async.cg.shared.global [%0], [%1], 16;" :: "r"(dst), "l"(src) : "memory");
}
#define LDSM4(r, addr) \
    asm volatile("ldmatrix.sync.aligned.m8n8.x4.shared.b16 {%0,%1,%2,%3}, [%4];" \
                 : "=r"((r)[0]), "=r"((r)[1]), "=r"((r)[2]), "=r"((r)[3]) : "r"(addr))
#define MMA16816(d, a, bb0, bb1) \
    asm volatile("mma.sync.aligned.m16n8k16.row.col.f32.f16.f16.f32 " \
                 "{%0,%1,%2,%3}, {%4,%5,%6,%7}, {%8,%9}, {%0,%1,%2,%3};" \
                 : "+f"((d)[0]), "+f"((d)[1]), "+f"((d)[2]), "+f"((d)[3]) \
                 : "r"((a)[0]), "r"((a)[1]), "r"((a)[2]), "r"((a)[3]), "r"(bb0), "r"(bb1))

__device__ __forceinline__ uint32_t pack_h2(float v0, float v1) {
    __half2 h = __floats2half2_rn(v0, v1);
    return *reinterpret_cast<uint32_t*>(&h);
}

// ---------------------------------------------------------------------------
// Kernel 1: u = concat(W)@Wa, c = b.Wa + ba  AND  W -> Wh^T fp16
// blocks [0,104): prep.  blocks [104,520): W convert.
// ---------------------------------------------------------------------------
__global__ void prepw_kernel(const float* __restrict__ W0, const float* __restrict__ b0,
                             const float* __restrict__ W1, const float* __restrict__ b1,
                             const float* __restrict__ W2, const float* __restrict__ b2,
                             const float* __restrict__ Wa, const float* __restrict__ ba)
{
    const int tid = threadIdx.x;
    if (blockIdx.x < 104) {
        int warp = blockIdx.x * 8 + (tid >> 5);
        int lane = tid & 31;
        if (warp < KTOT) {
            const float* row;
            if (warp < K0)           row = W0 + (size_t)warp * DOUT;
            else if (warp < K0+K1)   row = W1 + (size_t)(warp - K0) * DOUT;
            else                     row = W2 + (size_t)(warp - K0 - K1) * DOUT;
            float s = 0.f;
            for (int d = lane; d < DOUT; d += 32) s += row[d] * Wa[d];
            #pragma unroll
            for (int o = 16; o; o >>= 1) s += __shfl_xor_sync(0xffffffffu, s, o);
            if (lane == 0) g_u[warp] = s;
        } else if (warp < KTOT + 3) {
            int n = warp - KTOT;
            const float* b = (n == 0) ? b0 : ((n == 1) ? b1 : b2);
            float s = 0.f;
            for (int d = lane; d < DOUT; d += 32) s += b[d] * Wa[d];
            #pragma unroll
            for (int o = 16; o; o >>= 1) s += __shfl_xor_sync(0xffffffffu, s, o);
            if (lane == 0) g_c[n] = s + ba[0];
        }
    } else {
        int idx = (blockIdx.x - 104) * 256 + tid;   // [0, 256*416)
        if (idx < DOUT * (KPAD/2)) {
            int n  = idx / (KPAD/2);
            int k  = (idx % (KPAD/2)) * 2;
            float v0 = 0.f, v1 = 0.f;
            if (k < K0)        { v0 = W0[(size_t)k*DOUT + n];       v1 = W0[(size_t)(k+1)*DOUT + n]; }
            else if (k < 600)  { v0 = W1[(size_t)(k-300)*DOUT + n]; v1 = W1[(size_t)(k-299)*DOUT + n]; }
            else if (k < 800)  { v0 = W2[(size_t)(k-600)*DOUT + n]; v1 = W2[(size_t)(k-599)*DOUT + n]; }
            size_t off = ((size_t)n * KPAD + k) * 2;
            *(uint32_t*)((char*)g_Wh + off) = pack_h2(v0, v1);
        }
    }
}

// ---------------------------------------------------------------------------
// Kernel 2: logits -> softmax alphas, then alpha-scaled fp16 A (row-major)
// One warp per token.
// ---------------------------------------------------------------------------
__global__ void alpha_split_kernel(const int* __restrict__ ids,
                                   const float* __restrict__ E0,
                                   const float* __restrict__ E1,
                                   const float* __restrict__ E2)
{
    __shared__ float su[KTOT];
    __shared__ float sc[3];
    for (int i = threadIdx.x; i < KTOT; i += blockDim.x) su[i] = g_u[i];
    if (threadIdx.x < 3) sc[threadIdx.x] = g_c[threadIdx.x];
    __syncthreads();

    const int warp = blockIdx.x * 8 + (threadIdx.x >> 5);   // token id
    const int lane = threadIdx.x & 31;
    const size_t id = (size_t)ids[warp];

    const float* r0 = E0 + id * K0;
    const float* r1 = E1 + id * K1;
    const float* r2 = E2 + id * K2;

    float l0 = 0.f, l1 = 0.f, l2 = 0.f;
    for (int k = lane; k < K0; k += 32) l0 += r0[k] * su[k];
    for (int k = lane; k < K1; k += 32) l1 += r1[k] * su[K0 + k];
    for (int k = lane; k < K2; k += 32) l2 += r2[k] * su[K0 + K1 + k];
    #pragma unroll
    for (int o = 16; o; o >>= 1) {
        l0 += __shfl_xor_sync(0xffffffffu, l0, o);
        l1 += __shfl_xor_sync(0xffffffffu, l1, o);
        l2 += __shfl_xor_sync(0xffffffffu, l2, o);
    }
    l0 += sc[0]; l1 += sc[1]; l2 += sc[2];
    float m   = fmaxf(l0, fmaxf(l1, l2));
    float e0  = expf(l0 - m), e1 = expf(l1 - m), e2 = expf(l2 - m);
    float inv = 1.f / (e0 + e1 + e2);
    float a0 = e0 * inv, a1 = e1 * inv, a2 = e2 * inv;
    if (lane == 0) {
        g_alpha[warp*3 + 0] = a0;
        g_alpha[warp*3 + 1] = a1;
        g_alpha[warp*3 + 2] = a2;
    }

    #pragma unroll 1
    for (int c = 0; c < NCHUNK; c++) {
        int k = c * 64 + lane * 2;
        float v0 = 0.f, v1 = 0.f;
        if (k < K0)        { v0 = r0[k] * a0;       v1 = r0[k+1] * a0; }
        else if (k < 600)  { v0 = r1[k-300] * a1;   v1 = r1[k-299] * a1; }
        else if (k < 800)  { v0 = r2[k-600] * a2;   v1 = r2[k-599] * a2; }
        size_t off = ((size_t)warp * KPAD + k) * 2;
        *(uint32_t*)((char*)g_Ah + off) = pack_h2(v0, v1);
    }
}

// ---------------------------------------------------------------------------
// Kernel 3: HMMA GEMM.  out[16384,256] = A[16384,832] @ W^T (fp16 operands,
// fp32 accumulate) + alpha-weighted bias.
// CTA: 128x128, 8 warps (4x2), warp tile 32x64, BK=64, 3-stage cp.async.
// grid = (DOUT/BN, BT/BM): the 2 N-blocks of one M-tile are adjacent -> L2 A reuse.
// ---------------------------------------------------------------------------
__global__ void __launch_bounds__(256, 1)
gemm_kernel(const float* __restrict__ b0, const float* __restrict__ b1,
            const float* __restrict__ b2, float* __restrict__ out)
{
    extern __shared__ __align__(16) __half smem[];
    __shared__ float sBias[3][BN];
    __shared__ float sAl[3][BM];

    const int tid  = threadIdx.x;
    const int wid  = tid >> 5;
    const int lane = tid & 31;
    const int n0   = blockIdx.x * BN;
    const int m0   = blockIdx.y * BM;

    for (int i = tid; i < BN; i += 256) {
        sBias[0][i] = b0[n0 + i];
        sBias[1][i] = b1[n0 + i];
        sBias[2][i] = b2[n0 + i];
    }
    for (int i = tid; i < BM; i += 256) {
        int t = m0 + i;
        sAl[0][i] = g_alpha[t*3 + 0];
        sAl[1][i] = g_alpha[t*3 + 1];
        sAl[2][i] = g_alpha[t*3 + 2];
    }

    const uint32_t sb = su32(smem);

    // ---- pipelined load of one k-chunk stage ----
    auto loadStage = [&](int c, int stage) {
        const char* Ag = (const char*)g_Ah + (size_t)m0 * (KPAD*2) + c * 128;
        const char* Bg = (const char*)g_Wh + (size_t)n0 * (KPAD*2) + c * 128;
        const uint32_t As = sb + stage * STAGE_BYTES;
        const uint32_t Bs = As + BM * SPITCH * 2;
        #pragma unroll
        for (int i = 0; i < 4; i++) {
            int idx = tid + i * 256;
            int row = idx >> 3, cc = idx & 7;
            cpa16(As + (row * SPITCH + cc * 8) * 2, Ag + (size_t)row * (KPAD*2) + cc * 16);
        }
        #pragma unroll
        for (int i = 0; i < 4; i++) {
            int idx = tid + i * 256;
            int row = idx >> 3, cc = idx & 7;
            cpa16(Bs + (row * SPITCH + cc * 8) * 2, Bg + (size_t)row * (KPAD*2) + cc * 16);
        }
        asm volatile("cp.async.commit_group;" ::: "memory");
    };

    float acc[2][8][4];
    #pragma unroll
    for (int mt = 0; mt < 2; mt++)
        #pragma unroll
        for (int nt = 0; nt < 8; nt++)
            #pragma unroll
            for (int j = 0; j < 4; j++) acc[mt][nt][j] = 0.f;

    const int wm = (wid & 3) * 32;     // warp row base
    const int wn = (wid >> 2) * 64;    // warp col base
    const int lr = lane & 15;          // ldmatrix row
    const int lc = lane >> 4;          // ldmatrix k-half

    const int NITER = NCHUNK;          // 13
    loadStage(0, 0);
    loadStage(1, 1);

    #pragma unroll 1
    for (int iter = 0; iter < NITER; iter++) {
        asm volatile("cp.async.wait_group %0;" :: "n"(STAGES - 2));
        __syncthreads();
        if (iter + STAGES - 1 < NITER)
            loadStage(iter + STAGES - 1, (iter + STAGES - 1) % STAGES);

        const uint32_t As = sb + (iter % STAGES) * STAGE_BYTES;
        const uint32_t Bs = As + BM * SPITCH * 2;

        #pragma unroll
        for (int ks = 0; ks < 4; ks++) {
            uint32_t a[2][4], b[4][4];
            #pragma unroll
            for (int mt = 0; mt < 2; mt++) {
                uint32_t addr = As + ((wm + mt*16 + lr) * SPITCH + ks*16 + lc*8) * 2;
                LDSM4(a[mt], addr);
            }
            #pragma unroll
            for (int nt2 = 0; nt2 < 4; nt2++) {
                uint32_t addr = Bs + ((wn + nt2*16 + lr) * SPITCH + ks*16 + lc*8) * 2;
                LDSM4(b[nt2], addr);
            }
            #pragma unroll
            for (int mt = 0; mt < 2; mt++)
                #pragma unroll
                for (int nt = 0; nt < 8; nt++) {
                    const int g = nt >> 1, h = nt & 1;
                    MMA16816(acc[mt][nt], a[mt], b[g][h], b[g][2 + h]);
                }
        }
    }

    __syncthreads();

    // ---- epilogue: alpha-weighted bias + store ----
    #pragma unroll
    for (int mt = 0; mt < 2; mt++) {
        #pragma unroll
        for (int half = 0; half < 2; half++) {
            const int r  = wm + mt*16 + (lane >> 2) + half*8;
            const float a0 = sAl[0][r], a1 = sAl[1][r], a2 = sAl[2][r];
            float* orow = out + (size_t)(m0 + r) * DOUT + n0;
            #pragma unroll
            for (int nt = 0; nt < 8; nt++) {
                const int cidx = wn + nt*8 + (lane & 3)*2;
                float2 v;
                v.x = acc[mt][nt][half*2 + 0]
                    + a0*sBias[0][cidx]   + a1*sBias[1][cidx]   + a2*sBias[2][cidx];
                v.y = acc[mt][nt][half*2 + 1]
                    + a0*sBias[0][cidx+1] + a1*sBias[1][cidx+1] + a2*sBias[2][cidx+1];
                *(float2*)(orow + cidx) = v;
            }
        }
    }
}

// ---------------------------------------------------------------------------
extern "C" void kernel_launch(void* const* d_in, const int* in_sizes, int n_in,
                              void* d_out, int out_size)
{
    const int*   ids = (const int*)  d_in[0];
    const float* E0  = (const float*)d_in[1];
    const float* E1  = (const float*)d_in[2];
    const float* E2  = (const float*)d_in[3];
    const float* W0  = (const float*)d_in[4];
    const float* b0  = (const float*)d_in[5];
    const float* W1  = (const float*)d_in[6];
    const float* b1  = (const float*)d_in[7];
    const float* W2  = (const float*)d_in[8];
    const float* b2  = (const float*)d_in[9];
    const float* Wa  = (const float*)d_in[10];
    const float* ba  = (const float*)d_in[11];
    float* out = (float*)d_out;

    // Idempotent, host-side, enqueues nothing (safe under graph capture).
    cudaFuncSetAttribute(gemm_kernel, cudaFuncAttributeMaxDynamicSharedMemorySize, DYN_SMEM);

    prepw_kernel<<<520, 256>>>(W0, b0, W1, b1, W2, b2, Wa, ba);
    alpha_split_kernel<<<BT / 8, 256>>>(ids, E0, E1, E2);
    dim3 grid(DOUT / BN, BT / BM);   // n fast, m slow -> adjacent CTAs share A in L2
    gemm_kernel<<<grid, 256, DYN_SMEM>>>(b0, b1, b2, out);
}